// round 13
// baseline (speedup 1.0000x reference)
#include <cuda_runtime.h>
#include <cuda_fp16.h>
#include <cstdint>

#define NTOK 197
#define CIN 384
#define COUT 1152
#define TT 8
#define OUT_BT_STRIDE (COUT * NTOK)

__device__ float g_r[256 * COUT];
__device__ uint4 g_wh4[COUT * CIN / 8];   // weight fp16, [o][k] row-major

// ======================= helpers =======================
__device__ __forceinline__ uint32_t smem_u32(const void* p) {
    uint32_t a;
    asm("{ .reg .u64 t; cvta.to.shared.u64 t, %1; cvt.u32.u64 %0, t; }" : "=r"(a) : "l"(p));
    return a;
}
__device__ __forceinline__ uint32_t hsplit2(float a, float b, uint32_t& lo) {
    __half2 h = __floats2half2_rn(a, b);
    float2 hf = __half22float2(h);
    __half2 l = __floats2half2_rn(a - hf.x, b - hf.y);
    lo = *reinterpret_cast<uint32_t*>(&l);
    return *reinterpret_cast<uint32_t*>(&h);
}
__device__ __forceinline__ uint32_t h2pack(float a, float b) {
    __half2 h = __floats2half2_rn(a, b);
    return *reinterpret_cast<uint32_t*>(&h);
}
#define STS128(a, v0, v1, v2, v3) \
    asm volatile("st.shared.v4.b32 [%0], {%1, %2, %3, %4};" :: "r"(a), "r"(v0), "r"(v1), "r"(v2), "r"(v3) : "memory")
#define CP16(dst, src) \
    asm volatile("cp.async.cg.shared.global [%0], [%1], 16;" :: "r"(dst), "l"(src) : "memory")
#define CP_COMMIT() asm volatile("cp.async.commit_group;" ::: "memory")
#define CP_WAIT1() asm volatile("cp.async.wait_group 1;" ::: "memory")
#define LDSM4(r, a)                                                                   \
    asm volatile("ldmatrix.sync.aligned.m8n8.x4.shared.b16 {%0,%1,%2,%3}, [%4];"      \
        : "=r"((r)[0]), "=r"((r)[1]), "=r"((r)[2]), "=r"((r)[3]) : "r"(a))
#define MMA16816(d, a, b0, b1)                                                        \
    asm("mma.sync.aligned.m16n8k16.row.col.f32.f16.f16.f32 "                          \
        "{%0,%1,%2,%3}, {%4,%5,%6,%7}, {%8,%9}, {%0,%1,%2,%3};"                       \
        : "+f"((d)[0]), "+f"((d)[1]), "+f"((d)[2]), "+f"((d)[3])                      \
        : "r"((a)[0]), "r"((a)[1]), "r"((a)[2]), "r"((a)[3]), "r"(b0), "r"(b1))

// ======================= Kernel 0: weight fp16 convert =======================
__global__ void k_wsplit(const float* __restrict__ w) {
    int i = blockIdx.x * 256 + threadIdx.x;
    const float4 v0 = reinterpret_cast<const float4*>(w)[i * 2];
    const float4 v1 = reinterpret_cast<const float4*>(w)[i * 2 + 1];
    g_wh4[i] = make_uint4(h2pack(v0.x, v0.y), h2pack(v0.z, v0.w),
                          h2pack(v1.x, v1.y), h2pack(v1.z, v1.w));
}

// ======================= Kernel 1: routing (rf fused in) =======================
// grid = (144 o-tiles of 8, 8 b-groups of 4). Computes rf in-block from the cls
// data it already stages (every block redundantly, deterministic), then routing.
__global__ __launch_bounds__(256) void k_routing(const float* __restrict__ x,
                                                 const float* __restrict__ rf_w,
                                                 const float* __restrict__ rf_b,
                                                 const float* __restrict__ moe_w,
                                                 const float* __restrict__ moe_b) {
    extern __shared__ float rsm[];            // clsp[4][384][10] then spool[4][384]
    float* spool = rsm + 15360;
    __shared__ float srf[16];
    const int tid = threadIdx.x, lane = tid & 31, wid = tid >> 5;
    const int o = blockIdx.x * 8 + wid;
    const int b0 = blockIdx.y * 4;

    #pragma unroll 1
    for (int it = 0; it < 48; ++it) {
        int e = it * 256 + tid;
        int bi = e / 3072;
        int r2 = e - bi * 3072;
        int t = r2 / CIN;
        int c = r2 - t * CIN;
        rsm[bi * 3840 + c * 10 + t + 1] =
            x[(size_t)((b0 + bi) * TT + t) * NTOK * CIN + c];
    }
    #pragma unroll 1
    for (int it = 0; it < 12; ++it) {
        int e = it * 256 + tid;
        int bi = e / 768;
        int r2 = e - bi * 768;
        int c = r2 >> 1;
        rsm[bi * 3840 + c * 10 + (r2 & 1) * 9] = 0.f;
    }
    __syncthreads();

    // ---- fused rf: pooled = mean_t(cls); rf = pooled @ rf_w^T + rf_b ----
    #pragma unroll 1
    for (int e2 = tid; e2 < 1536; e2 += 256) {
        const int bi = e2 / 384, c = e2 - bi * 384;
        const float* cl = rsm + bi * 3840 + c * 10 + 1;
        float sm = 0.f;
        #pragma unroll
        for (int t = 0; t < TT; ++t) sm += cl[t];
        spool[e2] = sm * 0.125f;
    }
    __syncthreads();
    {
        const int combo = tid >> 4, sub = tid & 15;   // 16 combos x 16 threads
        const int bi = combo >> 2, e = combo & 3;
        float d = 0.f;
        #pragma unroll 1
        for (int c = sub; c < 384; c += 16)
            d += spool[bi * 384 + c] * rf_w[e * 384 + c];
        #pragma unroll
        for (int off = 8; off; off >>= 1) d += __shfl_xor_sync(0xffffffffu, d, off);
        if (sub == 0) srf[combo] = d + rf_b[e];
    }
    __syncthreads();

    float f[16];
    #pragma unroll
    for (int i = 0; i < 16; ++i) f[i] = srf[i];

    float vals[32];
    #pragma unroll
    for (int i = 0; i < 32; ++i) vals[i] = 0.f;

    #pragma unroll 1
    for (int ci = 0; ci < 12; ++ci) {
        const int c = ci * 32 + lane;
        float w[4][3];
        #pragma unroll
        for (int e = 0; e < 4; ++e) {
            const float* wp = moe_w + ((size_t)(e * COUT + o) * CIN + c) * 3;
            w[e][0] = wp[0]; w[e][1] = wp[1]; w[e][2] = wp[2];
        }
        #pragma unroll
        for (int bi = 0; bi < 4; ++bi) {
            const float f0 = f[bi * 4 + 0], f1 = f[bi * 4 + 1];
            const float f2 = f[bi * 4 + 2], f3 = f[bi * 4 + 3];
            const float wv0 = f0 * w[0][0] + f1 * w[1][0] + f2 * w[2][0] + f3 * w[3][0];
            const float wv1 = f0 * w[0][1] + f1 * w[1][1] + f2 * w[2][1] + f3 * w[3][1];
            const float wv2 = f0 * w[0][2] + f1 * w[1][2] + f2 * w[2][2] + f3 * w[3][2];
            const float* cl = rsm + bi * 3840 + c * 10;
            float cv[10];
            #pragma unroll
            for (int t = 0; t < 10; ++t) cv[t] = cl[t];
            #pragma unroll
            for (int t = 0; t < TT; ++t)
                vals[bi * 8 + t] += wv0 * cv[t] + wv1 * cv[t + 1] + wv2 * cv[t + 2];
        }
    }

    int cnt = 32;
    #pragma unroll
    for (int off = 16; off; off >>= 1) {
        cnt >>= 1;
        #pragma unroll 16
        for (int j = 0; j < cnt; ++j) {
            const float send = (lane & off) ? vals[j] : vals[j + cnt];
            const float other = __shfl_xor_sync(0xffffffffu, send, off);
            vals[j] = ((lane & off) ? vals[j + cnt] : vals[j]) + other;
        }
    }
    {
        const int bi = lane >> 3, t = lane & 7;
        float bo = 1.0f;
        #pragma unroll
        for (int e = 0; e < 4; ++e) bo += f[bi * 4 + e] * moe_b[e * COUT + o];
        g_r[(size_t)((b0 + bi) * TT + t) * COUT + o] = vals[0] + bo;
    }
}

// ======================= Kernel 2: main GEMM, persistent A =======================
// fp16 2-pass: D = (Ah + Al) * Wh. CTA = (branch s, 128m), loops 3 o-tiles.
// A: ALL 6 chunks resident in smem (6 x 32KB = 192KB, written once during
// o-tile 0, read 3x). B: 2-stage cp.async ring, 18 chunks total.
#define A_REG_STRIDE 32768
#define OFF_B 196608
#define B_STRIDE 16384
#define SMEM_MAIN (196608 + 32768 + 128)

__global__ __launch_bounds__(512, 1) void k_main(const float* __restrict__ x,
                                                 const float* __restrict__ bias,
                                                 float* __restrict__ out) {
    extern __shared__ char dsm[];
    const uint32_t sb = (smem_u32(dsm) + 127u) & ~127u;
    const int tid = threadIdx.x, lane = tid & 31, wid = tid >> 5;
    const int s = blockIdx.x;
    const int mBase = blockIdx.y * 128;

    // A loader mapping: 4 threads per row, 16 k each
    const int arow = tid >> 2;
    const int aq = tid & 3;
    const int am = mBase + arow;
    const int abt = am / NTOK;
    const float* axp = x + (size_t)am * CIN + aq * 16;
    const float* grp = g_r + (size_t)abt * COUT + s * CIN + aq * 16;

    uint32_t sA[2];
    {
        const uint32_t xm = (uint32_t)(arow & 7) * 16;
        #pragma unroll
        for (int g2 = 0; g2 < 2; ++g2)
            sA[g2] = (uint32_t)arow * 128 + (((uint32_t)(aq * 32 + g2 * 16)) ^ xm);
    }

    // warp tile: 4m x 4n warps, each 32m x 32o
    const int wm = (wid & 3) * 32;
    const int wn = (wid >> 2) * 32;

    const int lrow = lane & 15, lkh = lane >> 4;
    uint32_t aBase[2], aXm[2], bBase[2], bXm[2];
    #pragma unroll
    for (int mt = 0; mt < 2; ++mt) {
        const int row = wm + mt * 16 + lrow;
        aBase[mt] = (uint32_t)row * 128;
        aXm[mt] = (uint32_t)(row & 7) * 16;
    }
    #pragma unroll
    for (int nt = 0; nt < 2; ++nt) {
        const int row = wn + nt * 16 + lrow;
        bBase[nt] = (uint32_t)row * 128;
        bXm[nt] = (uint32_t)(row & 7) * 16;
    }

    float acc[2][4][4];
    #pragma unroll
    for (int i = 0; i < 2; ++i)
        #pragma unroll
        for (int j = 0; j < 4; ++j)
            #pragma unroll
            for (int e = 0; e < 4; ++e) acc[i][j][e] = 0.f;

    float4 xr[4], rr[4];

    auto ldgA = [&](int kOff) {
        const float4* xp4 = reinterpret_cast<const float4*>(axp + kOff);
        #pragma unroll
        for (int i = 0; i < 4; ++i) xr[i] = xp4[i];
    };
    auto ldgR = [&](int kOff) {
        const float4* rp4 = reinterpret_cast<const float4*>(grp + kOff);
        #pragma unroll
        for (int i = 0; i < 4; ++i) rr[i] = rp4[i];
    };
    auto stsA = [&](int region) {
        const uint32_t aH = sb + (uint32_t)region * A_REG_STRIDE;
        #pragma unroll
        for (int g2 = 0; g2 < 2; ++g2) {
            const float4 xa = xr[2 * g2], xb = xr[2 * g2 + 1];
            const float4 ra = rr[2 * g2], rb2 = rr[2 * g2 + 1];
            uint32_t h[4], l[4];
            h[0] = hsplit2(xa.x * ra.x, xa.y * ra.y, l[0]);
            h[1] = hsplit2(xa.z * ra.z, xa.w * ra.w, l[1]);
            h[2] = hsplit2(xb.x * rb2.x, xb.y * rb2.y, l[2]);
            h[3] = hsplit2(xb.z * rb2.z, xb.w * rb2.w, l[3]);
            STS128(aH + sA[g2], h[0], h[1], h[2], h[3]);
            STS128(aH + sA[g2] + 16384, l[0], l[1], l[2], l[3]);
        }
    };
    auto ldB = [&](int g) {
        const int ot = (g >= 12) ? 2 : (g >= 6 ? 1 : 0);
        const int kOff = (g - ot * 6) * 64;
        const int oB = s * 384 + ot * 128;
        const uint32_t bH = sb + OFF_B + (uint32_t)(g & 1) * B_STRIDE;
        const char* gh = (const char*)g_wh4;
        #pragma unroll
        for (int it = 0; it < 2; ++it) {
            const int idx = it * 512 + tid;          // 1024 16B-vectors (128 o x 8)
            const int ol = idx >> 3;
            const int kq = idx & 7;
            const size_t gb = ((size_t)(oB + ol) * CIN + kOff + kq * 8) * 2;
            const uint32_t off = (uint32_t)(ol * 128) +
                                 (((uint32_t)(kq * 16)) ^ ((uint32_t)(ol & 7) * 16));
            CP16(bH + off, gh + gb);
        }
    };
    auto compute = [&](int kc, int rb) {
        const uint32_t baseA = sb + (uint32_t)kc * A_REG_STRIDE;
        const uint32_t baseB = sb + OFF_B + (uint32_t)rb * B_STRIDE;
        #pragma unroll
        for (int kk = 0; kk < 4; ++kk) {
            const uint32_t kbl = (uint32_t)(kk * 32 + lkh * 16);
            uint32_t Ah[2][4], Al[2][4], Bh[2][4];
            #pragma unroll
            for (int mt = 0; mt < 2; ++mt) {
                const uint32_t ad = baseA + aBase[mt] + (kbl ^ aXm[mt]);
                LDSM4(Ah[mt], ad);
                LDSM4(Al[mt], ad + 16384);
            }
            #pragma unroll
            for (int nt = 0; nt < 2; ++nt) {
                const uint32_t bd = baseB + bBase[nt] + (kbl ^ bXm[nt]);
                LDSM4(Bh[nt], bd);
            }
            #pragma unroll
            for (int nt = 0; nt < 2; ++nt)
                #pragma unroll
                for (int mt = 0; mt < 2; ++mt) {
                    MMA16816(acc[mt][nt * 2],     Ah[mt], Bh[nt][0], Bh[nt][2]);
                    MMA16816(acc[mt][nt * 2 + 1], Ah[mt], Bh[nt][1], Bh[nt][3]);
                }
            #pragma unroll
            for (int nt = 0; nt < 2; ++nt)
                #pragma unroll
                for (int mt = 0; mt < 2; ++mt) {
                    MMA16816(acc[mt][nt * 2],     Al[mt], Bh[nt][0], Bh[nt][2]);
                    MMA16816(acc[mt][nt * 2 + 1], Al[mt], Bh[nt][1], Bh[nt][3]);
                }
        }
    };

    // ---- prologue ----
    ldgA(0); ldgR(0);
    ldB(0); CP_COMMIT();
    stsA(0);
    ldgA(64); ldgR(64);

    // ---- mainloop: 18 chunks (3 o-tiles x 6 k-chunks) ----
    int kc = 0, ot = 0;
    #pragma unroll 1
    for (int g = 0; g < 18; ++g) {
        __syncthreads();                  // all warps done with compute(g-1)
        if (g + 1 < 18) ldB(g + 1);       // region (g+1)&1 was freed by compute(g-1)
        CP_COMMIT();                      // real or empty: one group per iter
        if (g < 5) {
            stsA(g + 1);                  // A region g+1 (disjoint from all readers)
            if (g < 4) { ldgA((g + 2) * 64); ldgR((g + 2) * 64); }
        }
        CP_WAIT1();                       // B(g) complete (committed last iter)
        __syncthreads();                  // B(g) + A(g) visible to all
        compute(kc, g & 1);
        if (kc == 5) {
            // epilogue for o-tile ot
            const int oB = s * 384 + ot * 128;
            #pragma unroll
            for (int mt = 0; mt < 2; ++mt)
                #pragma unroll
                for (int rh = 0; rh < 2; ++rh) {
                    const int m = mBase + wm + mt * 16 + (lane >> 2) + rh * 8;
                    const int bt = m / NTOK;
                    const int n = m - bt * NTOK;
                    float* op = out + (size_t)bt * OUT_BT_STRIDE + n;
                    const float* rrp = g_r + (size_t)bt * COUT + oB + wn;
                    const float* bb = bias + oB + wn;
                    #pragma unroll
                    for (int nt2 = 0; nt2 < 4; ++nt2) {
                        const int c0 = nt2 * 8 + (lane & 3) * 2;
                        const float v0 = acc[mt][nt2][rh * 2 + 0] + bb[c0] * rrp[c0];
                        const float v1 = acc[mt][nt2][rh * 2 + 1] + bb[c0 + 1] * rrp[c0 + 1];
                        op[(size_t)(oB + wn + c0) * NTOK] = v0;
                        op[(size_t)(oB + wn + c0 + 1) * NTOK] = v1;
                    }
                }
            #pragma unroll
            for (int i = 0; i < 2; ++i)
                #pragma unroll
                for (int j = 0; j < 4; ++j)
                    #pragma unroll
                    for (int e = 0; e < 4; ++e) acc[i][j][e] = 0.f;
            kc = 0; ++ot;
        } else {
            ++kc;
        }
    }
}

// ======================= launch =======================
extern "C" void kernel_launch(void* const* d_in, const int* in_sizes, int n_in,
                              void* d_out, int out_size) {
    const float* x = (const float*)d_in[0];
    const float* rf_w = (const float*)d_in[1];
    const float* rf_b = (const float*)d_in[2];
    const float* moe_w = (const float*)d_in[3];
    const float* moe_b = (const float*)d_in[4];
    const float* weight = (const float*)d_in[5];
    const float* bias = (const float*)d_in[6];
    float* out = (float*)d_out;

    cudaFuncSetAttribute(k_main, cudaFuncAttributeMaxDynamicSharedMemorySize, SMEM_MAIN);
    cudaFuncSetAttribute(k_routing, cudaFuncAttributeMaxDynamicSharedMemorySize, 68608);

    k_wsplit<<<216, 256>>>(weight);
    k_routing<<<dim3(144, 8), 256, 68608>>>(x, rf_w, rf_b, moe_w, moe_b);
    k_main<<<dim3(3, 394), 512, SMEM_MAIN>>>(x, bias, out);
}